// round 7
// baseline (speedup 1.0000x reference)
#include <cuda_runtime.h>
#include <math.h>
#include <stdint.h>

#define NB     16
#define LSEQ   2048
#define NV     10
#define NPH    19
#define NCLS   190
#define NCLSP  192
#define NBUCK  3
#define NCHUNK 16
#define CHUNK  128
#define NE     (NV * NBUCK)        // 30 (dt,bucket) slices
#define ESZ    192                 // padded slice: idx = m*10+d (190 real)
#define ETAB_TOTAL (NE * ESZ)      // 5760
#define HIST_BLOCKS (NB * NCHUNK)  // 256
#define ETAB_BLOCKS ((ETAB_TOTAL + 255) / 256)  // 23

// ---------------- device scratch (static, allocation-free) ----------------
__device__ int      g_hist[NB * NCHUNK * NCLSP];
__device__ int      g_fo  [NB * NCHUNK * NCLSP];
__device__ uint16_t g_cbase[NB * NCHUNK * NCLSP];
__device__ int      g_tc1[NB * NCLS];
__device__ int      g_tc2[NB * NCLS];
__device__ __align__(16) float2 g_E[ETAB_TOTAL];   // {e, e*vv0} per (dt,bucket,m,d)

// ---------------- fp32 constants (no fp64 anywhere) ----------------
__device__ __forceinline__ float omega_f() { return 6.28318530717958647692f / 19.0f; }

// cancellation-free: cos(.3w)-cos(.7w) = 2 sin(.5w) sin(.2w); ATTN_SCALE = amp/2
__device__ __forceinline__ float asf_f() {
    float om = omega_f();
    return 2.302585092994046f / (4.0f * sinf(0.5f * om) * sinf(0.2f * om));
}
__device__ __forceinline__ float cosm_f(int m) {   // cos(om*m - phi), phi = om*10.3
    return cosf(omega_f() * ((float)m - 10.3f));
}
__device__ __forceinline__ float s_of(int d, float c, float e) {
    float h0 = c - e * (float)(d * d);
    float h1 = -(float)d;
    float r  = rsqrtf((h0 * h0 + h1 * h1) * 0.5f + 1e-6f);
    float hn0 = h0 * r;
    return hn0 * rsqrtf(hn0 * hn0 * 0.5f + 1e-6f);
}
__device__ __forceinline__ float vv0_of(int d, float c, float e, float v) {
    float h0 = c - e * (float)(d * d);
    float h1 = -(float)d;
    float r  = rsqrtf((h0 * h0 + h1 * h1) * 0.5f + 1e-6f);
    return h1 * r * v;
}

// ---------------- K_A: per-chunk histograms + first-occurrence, and E-table ----
__global__ void k_hist_tab(const int* __restrict__ tokens,
                           const float* __restrict__ C, const float* __restrict__ eps,
                           const float* __restrict__ v) {
    int tid = threadIdx.x;
    if (blockIdx.x < HIST_BLOCKS) {
        __shared__ int hist[NCLSP], fo[NCLSP];
        int b = blockIdx.x >> 4, ch = blockIdx.x & 15;
        if (tid < NCLSP) { hist[tid] = 0; fo[tid] = 1 << 20; }
        __syncthreads();
        if (tid < CHUNK) {
            int s   = ch * CHUNK + tid;
            int cls = tokens[b * LSEQ + s] + 10 * (s % NPH);
            atomicAdd(&hist[cls], 1);
            atomicMin(&fo[cls], tid);
        }
        __syncthreads();
        if (tid < NCLSP) {
            int o = (b * NCHUNK + ch) * NCLSP + tid;
            g_hist[o] = hist[tid];
            g_fo[o]   = fo[tid];
        }
    } else {
        int idx = (blockIdx.x - HIST_BLOCKS) * 256 + tid;
        if (idx < ETAB_TOTAL) {
            int j      = idx % ESZ;
            int slice  = idx / ESZ;
            int bucket = slice % NBUCK;
            int dt     = slice / NBUCK;
            int m = j / 10, d = j % 10;
            float2 r = make_float2(0.f, 0.f);
            if (m < NPH) {
                float c = C[0], e = eps[0], vd = v[0];
                float L   = asf_f() * s_of(dt, c, e) * s_of(d, c, e) * cosm_f(m);
                float off = -56.0f + 100.0f * (float)bucket;
                float x   = expf(fminf(L - off, 60.0f)); // clamp hits only count-0 entries
                r = make_float2(x, x * vv0_of(d, c, e, vd));
            }
            g_E[idx] = r;
        }
    }
}

// ---------------- K_B: per-batch prefix bases + bucket thresholds -------------
__global__ void k_thresh(const float* __restrict__ C, const float* __restrict__ eps) {
    int b = blockIdx.x, tid = threadIdx.x;
    __shared__ int   histS[NCHUNK * NCLSP];
    __shared__ int   foS[NCLSP];
    __shared__ float sdf[NV], cmf[NPH];
    __shared__ int   t1S[NCLS], t2S[NCLS];

    for (int i = tid; i < NCHUNK * NCLSP; i += 256)
        histS[i] = g_hist[b * NCHUNK * NCLSP + i];
    float c = C[0], e = eps[0];
    if (tid < NV)  sdf[tid] = s_of(tid, c, e);
    if (tid < NPH) cmf[tid] = cosm_f(tid);
    if (tid < NCLS) { t1S[tid] = 1 << 28; t2S[tid] = 1 << 28; }
    if (tid < NCLSP) {
        int mn = 1 << 28;
        for (int ch = 0; ch < NCHUNK; ch++)
            mn = min(mn, g_fo[(b * NCHUNK + ch) * NCLSP + tid] + ch * CHUNK);
        foS[tid] = mn;
        int run = 0;
        for (int ch = 0; ch < NCHUNK; ch++) {
            g_cbase[(b * NCHUNK + ch) * NCLSP + tid] = (uint16_t)run;
            run += histS[ch * NCLSP + tid];
        }
    }
    __syncthreads();

    float A = asf_f();
    for (int task = tid; task < NCLS * NPH; task += 256) {
        int q = task / NPH, p = task % NPH;
        int m = q % NPH - p; if (m < 0) m += NPH;
        float base = A * sdf[q / NPH] * cmf[m];
        int l1 = 1 << 28, l2 = 1 << 28;
        #pragma unroll
        for (int d = 0; d < NV; d++) {
            float L = base * sdf[d];
            int f = foS[d + 10 * p];
            if (L >= -6.0f)  l1 = min(l1, f);
            if (L >=  94.0f) l2 = min(l2, f);
        }
        atomicMin(&t1S[q], l1);
        atomicMin(&t2S[q], l2);
    }
    __syncthreads();
    if (tid < NCLS) {
        g_tc1[b * NCLS + tid] = t1S[tid];
        g_tc2[b * NCLS + tid] = t2S[tid];
    }
}

// ---------------- K_C: cumulative-histogram softmax + fused epilogue ----------
__global__ void __launch_bounds__(256) k_main(
    const int*   __restrict__ tokens,
    const float* __restrict__ C,        const float* __restrict__ eps,
    const float* __restrict__ o_scale,  const float* __restrict__ g_base,
    const float* __restrict__ g_slope,  const float* __restrict__ carry_amp,
    float* __restrict__ out)
{
    extern __shared__ uint8_t sh[];
    uint16_t* cnt_sh = (uint16_t*)sh;                        // CHUNK * NCLSP
    float2*   E_sh   = (float2*)(sh + CHUNK * NCLSP * 2);    // NE * ESZ
    __shared__ int tok_sh[CHUNK];

    int b = blockIdx.x >> 4, ch = blockIdx.x & 15;
    int tid = threadIdx.x;
    int T0  = ch * CHUNK;

    if (tid < CHUNK) tok_sh[tid] = tokens[b * LSEQ + T0 + tid];
    {   // preload the universal 45KB E-table (L2-hot across all 256 blocks)
        const float4* src = (const float4*)g_E;
        float4*       dst = (float4*)E_sh;
        #pragma unroll
        for (int i = 0; i < ETAB_TOTAL / 2 / 256 + 1; i++) {
            int j = tid + i * 256;
            if (j < ETAB_TOTAL / 2) dst[j] = src[j];
        }
    }
    __syncthreads();

    // build inclusive cumulative per-class counts (thread = class, serial 128 rows)
    if (tid < NCLSP) {
        int cnt = (int)g_cbase[(b * NCHUNK + ch) * NCLSP + tid];
        int ph  = T0 % NPH;
        #pragma unroll 4
        for (int p = 0; p < CHUNK; p++) {
            cnt += ((tok_sh[p] + 10 * ph) == tid);
            cnt_sh[p * NCLSP + tid] = (uint16_t)cnt;
            ph++; if (ph == NPH) ph = 0;
        }
    }
    __syncthreads();

    float c  = C[0],      ee = eps[0],     osc = o_scale[0];
    float ga = g_base[0], gc = g_slope[0], ca  = carry_amp[0];

    int w = tid >> 5, lane = tid & 31;
    const uint32_t* cnt32 = (const uint32_t*)cnt_sh;

    // per-lane class decomposition: classes lane*6 .. lane*6+5 -> (d,p)
    int dk[6], pk[6];
    #pragma unroll
    for (int k = 0; k < 6; k++) {
        int cls = lane * 6 + k;
        dk[k] = cls % 10;
        pk[k] = cls / 10;   // 19 for pad classes (count always 0, read harmless)
    }

    // preload bucket thresholds for this warp's 16 rows (lanes 0-15: tc1, 16-31: tc2)
    int myr  = lane & 15;
    int myt  = T0 + w * 16 + myr;
    int myq  = tok_sh[w * 16 + myr] * NPH + (myt % NPH);
    const int* tcp = (lane < 16) ? g_tc1 : g_tc2;
    int tcv = tcp[b * NCLS + myq];

    #pragma unroll 4
    for (int rr = 0; rr < 16; rr++) {
        int r  = w * 16 + rr;
        int t  = T0 + r;
        int dt = tok_sh[r];
        int tp = t % NPH;
        int tc1v = __shfl_sync(0xffffffffu, tcv, rr);
        int tc2v = __shfl_sync(0xffffffffu, tcv, rr + 16);
        int bucket = (t >= tc1v) + (t >= tc2v);
        const float2* Er = E_sh + (dt * NBUCK + bucket) * ESZ;

        int base = r * (NCLSP / 2) + lane * 3;   // conflict-free: 3 coprime 32
        uint32_t u0 = cnt32[base], u1 = cnt32[base + 1], u2 = cnt32[base + 2];
        float c0 = (float)(u0 & 0xffff), c1 = (float)(u0 >> 16);
        float c2 = (float)(u1 & 0xffff), c3 = (float)(u1 >> 16);
        float c4 = (float)(u2 & 0xffff), c5 = (float)(u2 >> 16);

        float den, num;
        {
            int m0 = tp - pk[0]; if (m0 < 0) m0 += NPH;
            int m1 = tp - pk[1]; if (m1 < 0) m1 += NPH;
            int m2 = tp - pk[2]; if (m2 < 0) m2 += NPH;
            int m3 = tp - pk[3]; if (m3 < 0) m3 += NPH;
            int m4 = tp - pk[4]; if (m4 < 0) m4 += NPH;
            int m5 = tp - pk[5]; if (m5 < 0) m5 += NPH;
            float2 e0 = Er[m0 * 10 + dk[0]];
            float2 e1 = Er[m1 * 10 + dk[1]];
            float2 e2 = Er[m2 * 10 + dk[2]];
            float2 e3 = Er[m3 * 10 + dk[3]];
            float2 e4 = Er[m4 * 10 + dk[4]];
            float2 e5 = Er[m5 * 10 + dk[5]];
            den = c0 * e0.x + c1 * e1.x + c2 * e2.x + c3 * e3.x + c4 * e4.x + c5 * e5.x;
            num = c0 * e0.y + c1 * e1.y + c2 * e2.y + c3 * e3.y + c4 * e4.y + c5 * e5.y;
        }
        #pragma unroll
        for (int o = 16; o; o >>= 1) {
            den += __shfl_xor_sync(0xffffffffu, den, o);
            num += __shfl_xor_sync(0xffffffffu, num, o);
        }
        float attn = num / den;

        // fused epilogue (mirrors reference fp32 math)
        float h0 = c - ee * (float)(dt * dt);
        float h1 = -(float)dt + osc * attn;
        float rn = rsqrtf((h0 * h0 + h1 * h1) * 0.5f + 1e-6f);
        float hn0 = h0 * rn, hn1 = h1 * rn;
        float g0  = hn0 * ga + hn1 * gc;
        float g1  = hn0 * (ga - gc / c) + hn1 * gc;
        float carry = ca * (fmaxf(g1, 0.f) * hn0 - fmaxf(g0, 0.f) * hn0);
        float h1c = h1 + carry;
        float r2  = rsqrtf((h0 * h0 + h1c * h1c) * 0.5f + 1e-6f);
        const float inv_cn = 0.7071067811865475f;
        float a0o = h0  * r2 * (0.1f * c * inv_cn);
        float a1o = h1c * r2 * (-c * 0.02f * inv_cn);
        if (lane < NV) {
            float t0  = c - ee * (float)(lane * lane);
            float t1v = -(float)lane;
            out[(b * LSEQ + t) * NV + lane] = a0o * t0 + a1o * t1v;
        }
    }
}

// ---------------- launch ----------------
extern "C" void kernel_launch(void* const* d_in, const int* in_sizes, int n_in,
                              void* d_out, int out_size) {
    const int*   tokens    = (const int*)  d_in[0];
    const float* C         = (const float*)d_in[1];
    const float* eps       = (const float*)d_in[2];
    const float* v         = (const float*)d_in[3];
    const float* o_scale   = (const float*)d_in[4];
    const float* g_base    = (const float*)d_in[5];
    const float* g_slope   = (const float*)d_in[6];
    const float* carry_amp = (const float*)d_in[7];
    float* out = (float*)d_out;

    const int smem = CHUNK * NCLSP * (int)sizeof(uint16_t)       // 49152
                   + ETAB_TOTAL * (int)sizeof(float2);           // 46080 -> 95232
    cudaFuncSetAttribute(k_main, cudaFuncAttributeMaxDynamicSharedMemorySize, smem);

    k_hist_tab<<<HIST_BLOCKS + ETAB_BLOCKS, 256>>>(tokens, C, eps, v);
    k_thresh<<<NB, 256>>>(C, eps);
    k_main<<<NB * NCHUNK, 256, smem>>>(tokens, C, eps, o_scale, g_base, g_slope,
                                       carry_amp, out);
}

// round 8
// speedup vs baseline: 1.0733x; 1.0733x over previous
#include <cuda_runtime.h>
#include <math.h>
#include <stdint.h>

#define NB     16
#define LSEQ   2048
#define NV     10
#define NPH    19
#define NCLS   190
#define NCLSP  192
#define NBUCK  3
#define NCHUNK 16
#define CHUNK  128
#define TAB_TOTAL (NCLS * NBUCK * NCLSP)          // 109440
#define TAB_BLOCKS ((TAB_TOTAL + 255) / 256)      // 428

// ---------------- device scratch (static, allocation-free) ----------------
__device__ int      g_hist[NB * NCHUNK * NCLSP];
__device__ int      g_fo  [NB * NCHUNK * NCLSP];
__device__ uint16_t g_cbase[NB * NCHUNK * NCLSP];
__device__ int      g_tc1[NB * NCLS];
__device__ int      g_tc2[NB * NCLS];
__device__ __align__(16) float2 g_tab[TAB_TOTAL]; // {e, e*vv0} per (q,bucket,cls)

// ---------------- fp32 constants (no fp64 anywhere) ----------------
__device__ __forceinline__ float omega_f() { return 6.28318530717958647692f / 19.0f; }
// cancellation-free: cos(.3w)-cos(.7w) = 2 sin(.5w) sin(.2w); ATTN_SCALE = amp/2
__device__ __forceinline__ float asf_f() {
    float om = omega_f();
    return 2.302585092994046f / (4.0f * sinf(0.5f * om) * sinf(0.2f * om));
}
__device__ __forceinline__ float cosm_f(int m) {   // cos(om*m - phi), phi = om*10.3
    return cosf(omega_f() * ((float)m - 10.3f));
}
__device__ __forceinline__ float s_of(int d, float c, float e) {
    float h0 = c - e * (float)(d * d);
    float h1 = -(float)d;
    float r  = rsqrtf((h0 * h0 + h1 * h1) * 0.5f + 1e-6f);
    float hn0 = h0 * r;
    return hn0 * rsqrtf(hn0 * hn0 * 0.5f + 1e-6f);
}
__device__ __forceinline__ float vv0_of(int d, float c, float e, float v) {
    float h0 = c - e * (float)(d * d);
    float h1 = -(float)d;
    float r  = rsqrtf((h0 * h0 + h1 * h1) * 0.5f + 1e-6f);
    return h1 * r * v;
}

// ---------------- K1: per-chunk histogram + first-occurrence ----------------
__global__ __launch_bounds__(128) void k_hist(const int* __restrict__ tokens) {
    __shared__ int hist[NCLSP], fo[NCLSP];
    int tid = threadIdx.x;
    int b = blockIdx.x >> 4, ch = blockIdx.x & 15;
    hist[tid] = 0; fo[tid] = 1 << 20;
    if (tid < NCLSP - 128) { hist[tid + 128] = 0; fo[tid + 128] = 1 << 20; }
    __syncthreads();
    int s   = ch * CHUNK + tid;
    int cls = tokens[b * LSEQ + s] + 10 * (s % NPH);
    atomicAdd(&hist[cls], 1);
    atomicMin(&fo[cls], tid);
    __syncthreads();
    int o = (b * NCHUNK + ch) * NCLSP;
    g_hist[o + tid] = hist[tid];
    g_fo[o + tid]   = fo[tid];
    if (tid < NCLSP - 128) {
        g_hist[o + tid + 128] = hist[tid + 128];
        g_fo[o + tid + 128]   = fo[tid + 128];
    }
}

// ---------------- K2: thresholds + prefix bases (blocks 0-15), table (rest) ----
__global__ __launch_bounds__(256) void k_thresh_tab(
        const float* __restrict__ C, const float* __restrict__ eps,
        const float* __restrict__ v) {
    int tid = threadIdx.x;
    if (blockIdx.x < NB) {
        int b = blockIdx.x;
        __shared__ int   foS[NCLSP];
        __shared__ float sdf[NV], cmf[NPH];
        __shared__ int   t1S[NCLS], t2S[NCLS];

        float c = C[0], e = eps[0];
        if (tid < NV)  sdf[tid] = s_of(tid, c, e);
        if (tid < NPH) cmf[tid] = cosm_f(tid);
        if (tid < NCLS) { t1S[tid] = 1 << 28; t2S[tid] = 1 << 28; }
        if (tid < NCLSP) {
            int mn = 1 << 28, run = 0;
            #pragma unroll
            for (int ch = 0; ch < NCHUNK; ch++) {
                int o = (b * NCHUNK + ch) * NCLSP + tid;
                mn = min(mn, g_fo[o] + ch * CHUNK);
                g_cbase[o] = (uint16_t)run;
                run += g_hist[o];
            }
            foS[tid] = mn;
        }
        __syncthreads();

        float A = asf_f();
        for (int task = tid; task < NCLS * NPH; task += 256) {
            int q = task / NPH, p = task % NPH;
            int m = q % NPH - p; if (m < 0) m += NPH;
            float base = A * sdf[q / NPH] * cmf[m];
            int l1 = 1 << 28, l2 = 1 << 28;
            #pragma unroll
            for (int d = 0; d < NV; d++) {
                float L = base * sdf[d];
                int f = foS[d + 10 * p];
                if (L >= -6.0f)  l1 = min(l1, f);
                if (L >=  94.0f) l2 = min(l2, f);
            }
            atomicMin(&t1S[q], l1);
            atomicMin(&t2S[q], l2);
        }
        __syncthreads();
        if (tid < NCLS) {
            g_tc1[b * NCLS + tid] = t1S[tid];
            g_tc2[b * NCLS + tid] = t2S[tid];
        }
    } else {
        int idx = (blockIdx.x - NB) * 256 + tid;
        if (idx < TAB_TOTAL) {
            int cls    = idx % NCLSP;
            int rest   = idx / NCLSP;
            int bucket = rest % NBUCK;
            int q      = rest / NBUCK;
            float2 r = make_float2(0.f, 0.f);
            if (cls < NCLS) {
                int dt = q / NPH, tp = q % NPH;
                int d  = cls % 10, p = cls / 10;
                int m  = tp - p; if (m < 0) m += NPH;
                float c = C[0], e = eps[0], vd = v[0];
                float L   = asf_f() * s_of(dt, c, e) * s_of(d, c, e) * cosm_f(m);
                float off = -56.0f + 100.0f * (float)bucket;
                float x   = expf(fminf(L - off, 60.0f)); // clamp hits only count-0 entries
                r = make_float2(x, x * vv0_of(d, c, e, vd));
            }
            g_tab[idx] = r;
        }
    }
}

// ---------------- K3: cumulative-histogram softmax + fused epilogue ----------
__global__ void __launch_bounds__(256) k_main(
    const int*   __restrict__ tokens,
    const float* __restrict__ C,        const float* __restrict__ eps,
    const float* __restrict__ o_scale,  const float* __restrict__ g_base,
    const float* __restrict__ g_slope,  const float* __restrict__ carry_amp,
    float* __restrict__ out)
{
    extern __shared__ uint16_t cnt_sh[];   // [CHUNK][NCLSP] inclusive cumulative counts
    __shared__ int tok_sh[CHUNK];
    __shared__ int cls_sh[CHUNK];

    int b   = blockIdx.x >> 4;
    int ch  = blockIdx.x & 15;
    int tid = threadIdx.x;
    int T0  = ch * CHUNK;

    if (tid < CHUNK) {
        int tk = tokens[b * LSEQ + T0 + tid];
        tok_sh[tid] = tk;
        cls_sh[tid] = tk + 10 * ((T0 + tid) % NPH);
    }
    __syncthreads();

    // build inclusive cumulative per-class counts (thread = class, serial 128 rows)
    if (tid < NCLSP) {
        int cnt = (int)g_cbase[(b * NCHUNK + ch) * NCLSP + tid];
        #pragma unroll 8
        for (int p = 0; p < CHUNK; p++) {
            cnt += (cls_sh[p] == tid);
            cnt_sh[p * NCLSP + tid] = (uint16_t)cnt;
        }
    }
    __syncthreads();

    float c  = C[0],      ee = eps[0],     osc = o_scale[0];
    float ga = g_base[0], gc = g_slope[0], ca  = carry_amp[0];

    int w = tid >> 5, lane = tid & 31;
    const uint32_t* cnt32 = (const uint32_t*)cnt_sh;

    // preload bucket thresholds for this warp's 16 rows (lanes 0-15: tc1, 16-31: tc2)
    int myr  = lane & 15;
    int myt  = T0 + w * 16 + myr;
    int myq  = tok_sh[w * 16 + myr] * NPH + (myt % NPH);
    const int* tcp = (lane < 16) ? g_tc1 : g_tc2;
    int tcv = tcp[b * NCLS + myq];

    #pragma unroll 4
    for (int rr = 0; rr < 16; rr++) {
        int r  = w * 16 + rr;
        int t  = T0 + r;
        int dt = tok_sh[r];
        int q  = dt * NPH + (t % NPH);
        int tc1v = __shfl_sync(0xffffffffu, tcv, rr);
        int tc2v = __shfl_sync(0xffffffffu, tcv, rr + 16);
        int bucket = (t >= tc1v) + (t >= tc2v);

        const float4* Tb = (const float4*)(g_tab + (q * NBUCK + bucket) * NCLSP) + lane * 3;
        float4 e0 = __ldg(Tb + 0);
        float4 e1 = __ldg(Tb + 1);
        float4 e2 = __ldg(Tb + 2);

        int base = r * (NCLSP / 2) + lane * 3;   // conflict-free: 3 coprime 32
        uint32_t u0 = cnt32[base], u1 = cnt32[base + 1], u2 = cnt32[base + 2];
        float c0 = (float)(u0 & 0xffff), c1 = (float)(u0 >> 16);
        float c2 = (float)(u1 & 0xffff), c3 = (float)(u1 >> 16);
        float c4 = (float)(u2 & 0xffff), c5 = (float)(u2 >> 16);

        float den = c0 * e0.x + c1 * e0.z + c2 * e1.x + c3 * e1.z + c4 * e2.x + c5 * e2.z;
        float num = c0 * e0.y + c1 * e0.w + c2 * e1.y + c3 * e1.w + c4 * e2.y + c5 * e2.w;

        #pragma unroll
        for (int o = 16; o; o >>= 1) {
            den += __shfl_xor_sync(0xffffffffu, den, o);
            num += __shfl_xor_sync(0xffffffffu, num, o);
        }
        float attn = num / den;

        // fused epilogue (mirrors reference fp32 math exactly)
        float h0 = c - ee * (float)(dt * dt);
        float h1 = -(float)dt + osc * attn;
        float rn = rsqrtf((h0 * h0 + h1 * h1) * 0.5f + 1e-6f);
        float hn0 = h0 * rn, hn1 = h1 * rn;
        float g0  = hn0 * ga + hn1 * gc;
        float g1  = hn0 * (ga - gc / c) + hn1 * gc;
        float carry = ca * (fmaxf(g1, 0.f) * hn0 - fmaxf(g0, 0.f) * hn0);
        float h1c = h1 + carry;
        float r2  = rsqrtf((h0 * h0 + h1c * h1c) * 0.5f + 1e-6f);
        const float inv_cn = 0.7071067811865475f;      // 1/sqrt(MODEL_DIM)
        float a0o = h0  * r2 * (0.1f * c * inv_cn);
        float a1o = h1c * r2 * (-c * 0.02f * inv_cn);  // -c/(50*sqrt2)
        if (lane < NV) {
            float t0  = c - ee * (float)(lane * lane);
            float t1v = -(float)lane;
            out[(b * LSEQ + t) * NV + lane] = a0o * t0 + a1o * t1v;
        }
    }
}

// ---------------- launch ----------------
extern "C" void kernel_launch(void* const* d_in, const int* in_sizes, int n_in,
                              void* d_out, int out_size) {
    const int*   tokens    = (const int*)  d_in[0];
    const float* C         = (const float*)d_in[1];
    const float* eps       = (const float*)d_in[2];
    const float* v         = (const float*)d_in[3];
    const float* o_scale   = (const float*)d_in[4];
    const float* g_base    = (const float*)d_in[5];
    const float* g_slope   = (const float*)d_in[6];
    const float* carry_amp = (const float*)d_in[7];
    float* out = (float*)d_out;

    const int smem = CHUNK * NCLSP * (int)sizeof(uint16_t);   // 49152
    cudaFuncSetAttribute(k_main, cudaFuncAttributeMaxDynamicSharedMemorySize, smem);

    k_hist<<<NB * NCHUNK, 128>>>(tokens);
    k_thresh_tab<<<NB + TAB_BLOCKS, 256>>>(C, eps, v);
    k_main<<<NB * NCHUNK, 256, smem>>>(tokens, C, eps, o_scale, g_base, g_slope,
                                       carry_amp, out);
}

// round 9
// speedup vs baseline: 1.2279x; 1.1440x over previous
#include <cuda_runtime.h>
#include <math.h>
#include <stdint.h>

#define NB     16
#define LSEQ   2048
#define NV     10
#define NPH    19
#define NCLS   190
#define NCLSP  192
#define NBUCK  3
#define NCHUNK 16
#define CHUNK  128
#define TAB_TOTAL (NCLS * NBUCK * NCLSP)          // 109440
#define TAB_BLOCKS ((TAB_TOTAL + 255) / 256)      // 428
#define HIST_BLOCKS 128                           // 2 chunks per block

// ---------------- device scratch (static, allocation-free) ----------------
__device__ int g_hist[NB * NCHUNK * NCLSP];
__device__ int g_fo  [NB * NCHUNK * NCLSP];
__device__ __align__(16) float2 g_tab[TAB_TOTAL]; // {e, e*vv0} per (q,bucket,cls)

// ---------------- fp32 constants (no fp64 anywhere) ----------------
__device__ __forceinline__ float omega_f() { return 6.28318530717958647692f / 19.0f; }
// cancellation-free: cos(.3w)-cos(.7w) = 2 sin(.5w) sin(.2w); ATTN_SCALE = amp/2
__device__ __forceinline__ float asf_f() {
    float om = omega_f();
    return 2.302585092994046f / (4.0f * sinf(0.5f * om) * sinf(0.2f * om));
}
__device__ __forceinline__ float cosm_f(int m) {   // cos(om*m - phi), phi = om*10.3
    return cosf(omega_f() * ((float)m - 10.3f));
}
__device__ __forceinline__ float s_of(int d, float c, float e) {
    float h0 = c - e * (float)(d * d);
    float h1 = -(float)d;
    float r  = rsqrtf((h0 * h0 + h1 * h1) * 0.5f + 1e-6f);
    float hn0 = h0 * r;
    return hn0 * rsqrtf(hn0 * hn0 * 0.5f + 1e-6f);
}
__device__ __forceinline__ float vv0_of(int d, float c, float e, float v) {
    float h0 = c - e * (float)(d * d);
    float h1 = -(float)d;
    float r  = rsqrtf((h0 * h0 + h1 * h1) * 0.5f + 1e-6f);
    return h1 * r * v;
}

// ---------------- K1: per-chunk hist/first-occurrence (blocks 0-127)
// ----------------     + exp table (blocks 128+), fused, independent parts ----
__global__ __launch_bounds__(256) void k1(const int* __restrict__ tokens,
                                          const float* __restrict__ C,
                                          const float* __restrict__ eps,
                                          const float* __restrict__ v) {
    int tid = threadIdx.x;
    if (blockIdx.x < HIST_BLOCKS) {
        __shared__ int hist[2][NCLSP], fo[2][NCLSP];
        int b   = blockIdx.x >> 3;           // 16 batches * 8 blocks
        int ch0 = (blockIdx.x & 7) * 2;      // two chunks per block
        if (tid < NCLSP) {
            hist[0][tid] = 0; fo[0][tid] = 1 << 20;
            hist[1][tid] = 0; fo[1][tid] = 1 << 20;
        }
        __syncthreads();
        int s    = ch0 * CHUNK + tid;        // 256 positions = 2 chunks
        int half = tid >> 7;
        int cls  = tokens[b * LSEQ + s] + 10 * (s % NPH);
        atomicAdd(&hist[half][cls], 1);
        atomicMin(&fo[half][cls], tid & 127);
        __syncthreads();
        if (tid < NCLSP) {
            int o = (b * NCHUNK + ch0) * NCLSP + tid;
            g_hist[o] = hist[0][tid];           g_fo[o] = fo[0][tid];
            g_hist[o + NCLSP] = hist[1][tid];   g_fo[o + NCLSP] = fo[1][tid];
        }
    } else {
        int idx = (blockIdx.x - HIST_BLOCKS) * 256 + tid;
        if (idx < TAB_TOTAL) {
            int cls    = idx % NCLSP;
            int rest   = idx / NCLSP;
            int bucket = rest % NBUCK;
            int q      = rest / NBUCK;
            float2 r = make_float2(0.f, 0.f);
            if (cls < NCLS) {
                int dt = q / NPH, tp = q % NPH;
                int d  = cls % 10, p = cls / 10;
                int m  = tp - p; if (m < 0) m += NPH;
                float c = C[0], e = eps[0], vd = v[0];
                float L   = asf_f() * s_of(dt, c, e) * s_of(d, c, e) * cosm_f(m);
                float off = -56.0f + 100.0f * (float)bucket;
                float x   = expf(fminf(L - off, 60.0f)); // clamp hits only count-0 entries
                r = make_float2(x, x * vv0_of(d, c, e, vd));
            }
            g_tab[idx] = r;
        }
    }
}

// ---------------- K2: prefix + thresholds + cumulative-histogram softmax ------
__global__ void __launch_bounds__(256) k_main(
    const int*   __restrict__ tokens,
    const float* __restrict__ C,        const float* __restrict__ eps,
    const float* __restrict__ o_scale,  const float* __restrict__ g_base,
    const float* __restrict__ g_slope,  const float* __restrict__ carry_amp,
    float* __restrict__ out)
{
    extern __shared__ uint16_t cnt_sh[];   // [CHUNK][NCLSP] inclusive cumulative counts
    __shared__ int   tok_sh[CHUNK];
    __shared__ int   cls_sh[CHUNK];
    __shared__ int   foS[NCLSP];
    __shared__ int   t1S[NCLS], t2S[NCLS];
    __shared__ float sdf[NV], cmf[NPH];

    int b   = blockIdx.x >> 4;
    int ch  = blockIdx.x & 15;
    int tid = threadIdx.x;
    int T0  = ch * CHUNK;

    float c  = C[0], ee = eps[0];

    if (tid < CHUNK) {
        int tk = tokens[b * LSEQ + T0 + tid];
        tok_sh[tid] = tk;
        cls_sh[tid] = tk + 10 * ((T0 + tid) % NPH);
    }
    if (tid < NV)  sdf[tid] = s_of(tid, c, ee);
    if (tid < NPH) cmf[tid] = cosm_f(tid);
    if (tid < NCLS) { t1S[tid] = 1 << 28; t2S[tid] = 1 << 28; }

    // per-class prefix base (registers) + global first-occurrence (smem)
    int basec = 0;
    if (tid < NCLSP) {
        int mn = 1 << 28;
        #pragma unroll
        for (int cc = 0; cc < NCHUNK; cc++) {
            int o = (b * NCHUNK + cc) * NCLSP + tid;
            int h = g_hist[o];
            int f = g_fo[o];
            if (cc < ch) basec += h;          // ch is uniform per block
            mn = min(mn, f + cc * CHUNK);
        }
        foS[tid] = mn;
    }
    __syncthreads();

    // bucket thresholds for all 190 query classes (3610 tasks over 256 threads)
    float A = asf_f();
    for (int task = tid; task < NCLS * NPH; task += 256) {
        int q = task / NPH, p = task % NPH;
        int m = q % NPH - p; if (m < 0) m += NPH;
        float base = A * sdf[q / NPH] * cmf[m];
        int l1 = 1 << 28, l2 = 1 << 28;
        #pragma unroll
        for (int d = 0; d < NV; d++) {
            float L = base * sdf[d];
            int f = foS[d + 10 * p];
            if (L >= -6.0f)  l1 = min(l1, f);
            if (L >=  94.0f) l2 = min(l2, f);
        }
        atomicMin(&t1S[q], l1);
        atomicMin(&t2S[q], l2);
    }

    // inclusive cumulative per-class counts (thread = class, serial 128 rows)
    if (tid < NCLSP) {
        int cnt = basec;
        #pragma unroll 8
        for (int p = 0; p < CHUNK; p++) {
            cnt += (cls_sh[p] == tid);
            cnt_sh[p * NCLSP + tid] = (uint16_t)cnt;
        }
    }
    __syncthreads();

    float osc = o_scale[0];
    float ga = g_base[0], gc = g_slope[0], ca = carry_amp[0];

    int w = tid >> 5, lane = tid & 31;
    const uint32_t* cnt32 = (const uint32_t*)cnt_sh;

    #pragma unroll 4
    for (int rr = 0; rr < 16; rr++) {
        int r  = w * 16 + rr;
        int t  = T0 + r;
        int dt = tok_sh[r];
        int q  = dt * NPH + (t % NPH);
        int bucket = (t >= t1S[q]) + (t >= t2S[q]);

        const float4* Tb = (const float4*)(g_tab + (q * NBUCK + bucket) * NCLSP) + lane * 3;
        float4 e0 = __ldg(Tb + 0);
        float4 e1 = __ldg(Tb + 1);
        float4 e2 = __ldg(Tb + 2);

        int base = r * (NCLSP / 2) + lane * 3;   // conflict-free: 3 coprime 32
        uint32_t u0 = cnt32[base], u1 = cnt32[base + 1], u2 = cnt32[base + 2];
        float c0 = (float)(u0 & 0xffff), c1 = (float)(u0 >> 16);
        float c2 = (float)(u1 & 0xffff), c3 = (float)(u1 >> 16);
        float c4 = (float)(u2 & 0xffff), c5 = (float)(u2 >> 16);

        float den = c0 * e0.x + c1 * e0.z + c2 * e1.x + c3 * e1.z + c4 * e2.x + c5 * e2.z;
        float num = c0 * e0.y + c1 * e0.w + c2 * e1.y + c3 * e1.w + c4 * e2.y + c5 * e2.w;

        #pragma unroll
        for (int o = 16; o; o >>= 1) {
            den += __shfl_xor_sync(0xffffffffu, den, o);
            num += __shfl_xor_sync(0xffffffffu, num, o);
        }
        float attn = num / den;

        // fused epilogue (mirrors reference fp32 math exactly)
        float h0 = c - ee * (float)(dt * dt);
        float h1 = -(float)dt + osc * attn;
        float rn = rsqrtf((h0 * h0 + h1 * h1) * 0.5f + 1e-6f);
        float hn0 = h0 * rn, hn1 = h1 * rn;
        float g0  = hn0 * ga + hn1 * gc;
        float g1  = hn0 * (ga - gc / c) + hn1 * gc;
        float carry = ca * (fmaxf(g1, 0.f) * hn0 - fmaxf(g0, 0.f) * hn0);
        float h1c = h1 + carry;
        float r2  = rsqrtf((h0 * h0 + h1c * h1c) * 0.5f + 1e-6f);
        const float inv_cn = 0.7071067811865475f;      // 1/sqrt(MODEL_DIM)
        float a0o = h0  * r2 * (0.1f * c * inv_cn);
        float a1o = h1c * r2 * (-c * 0.02f * inv_cn);  // -c/(50*sqrt2)
        if (lane < NV) {
            float t0  = c - ee * (float)(lane * lane);
            float t1v = -(float)lane;
            out[(b * LSEQ + t) * NV + lane] = a0o * t0 + a1o * t1v;
        }
    }
}

// ---------------- launch ----------------
extern "C" void kernel_launch(void* const* d_in, const int* in_sizes, int n_in,
                              void* d_out, int out_size) {
    const int*   tokens    = (const int*)  d_in[0];
    const float* C         = (const float*)d_in[1];
    const float* eps       = (const float*)d_in[2];
    const float* v         = (const float*)d_in[3];
    const float* o_scale   = (const float*)d_in[4];
    const float* g_base    = (const float*)d_in[5];
    const float* g_slope   = (const float*)d_in[6];
    const float* carry_amp = (const float*)d_in[7];
    float* out = (float*)d_out;

    const int smem = CHUNK * NCLSP * (int)sizeof(uint16_t);   // 49152
    cudaFuncSetAttribute(k_main, cudaFuncAttributeMaxDynamicSharedMemorySize, smem);

    k1<<<HIST_BLOCKS + TAB_BLOCKS, 256>>>(tokens, C, eps, v);
    k_main<<<NB * NCHUNK, 256, smem>>>(tokens, C, eps, o_scale, g_base, g_slope,
                                       carry_amp, out);
}

// round 10
// speedup vs baseline: 1.3148x; 1.0708x over previous
#include <cuda_runtime.h>
#include <math.h>
#include <stdint.h>

#define NB     16
#define LSEQ   2048
#define NV     10
#define NPH    19
#define NCLS   190
#define NCLSP  192
#define NBUCK  3
#define NCHUNK 16
#define CHUNK  128
#define NSUB   32                                 // 64-position subchunks per batch
#define SUB    64
#define TAB_TOTAL (NCLS * NBUCK * NCLSP)          // 109440
#define TAB_BLOCKS ((TAB_TOTAL + 255) / 256)      // 428
#define HIST_BLOCKS 128                           // 4 subchunks (256 pos) per block

// ---------------- device scratch (static, allocation-free) ----------------
__device__ int g_hist[NB * NSUB * NCLSP];
__device__ int g_fo  [NB * NSUB * NCLSP];
__device__ __align__(16) float2 g_tab[TAB_TOTAL]; // {e, e*vv0} per (q,bucket,cls)

// ---------------- fp32 constants (no fp64 anywhere) ----------------
__device__ __forceinline__ float omega_f() { return 6.28318530717958647692f / 19.0f; }
// cancellation-free: cos(.3w)-cos(.7w) = 2 sin(.5w) sin(.2w); ATTN_SCALE = amp/2
__device__ __forceinline__ float asf_f() {
    float om = omega_f();
    return 2.302585092994046f / (4.0f * sinf(0.5f * om) * sinf(0.2f * om));
}
__device__ __forceinline__ float cosm_f(int m) {   // cos(om*m - phi), phi = om*10.3
    return cosf(omega_f() * ((float)m - 10.3f));
}
__device__ __forceinline__ float s_of(int d, float c, float e) {
    float h0 = c - e * (float)(d * d);
    float h1 = -(float)d;
    float r  = rsqrtf((h0 * h0 + h1 * h1) * 0.5f + 1e-6f);
    float hn0 = h0 * r;
    return hn0 * rsqrtf(hn0 * hn0 * 0.5f + 1e-6f);
}
__device__ __forceinline__ float vv0_of(int d, float c, float e, float v) {
    float h0 = c - e * (float)(d * d);
    float h1 = -(float)d;
    float r  = rsqrtf((h0 * h0 + h1 * h1) * 0.5f + 1e-6f);
    return h1 * r * v;
}

// ---------------- K1: sub-chunk hist/first-occurrence (blocks 0-127)
// ----------------     + exp table (blocks 128+), fused, independent parts ----
__global__ __launch_bounds__(256) void k1(const int* __restrict__ tokens,
                                          const float* __restrict__ C,
                                          const float* __restrict__ eps,
                                          const float* __restrict__ v) {
    int tid = threadIdx.x;
    if (blockIdx.x < HIST_BLOCKS) {
        __shared__ int hist[4][NCLSP], fo[4][NCLSP];
        int b    = blockIdx.x >> 3;          // 16 batches * 8 blocks
        int sub0 = (blockIdx.x & 7) * 4;     // four 64-pos subchunks per block
        if (tid < NCLSP) {
            #pragma unroll
            for (int h = 0; h < 4; h++) { hist[h][tid] = 0; fo[h][tid] = 1 << 20; }
        }
        __syncthreads();
        int s    = sub0 * SUB + tid;         // 256 positions = 4 subchunks
        int half = tid >> 6;
        int cls  = tokens[b * LSEQ + s] + 10 * (s % NPH);
        atomicAdd(&hist[half][cls], 1);
        atomicMin(&fo[half][cls], tid & 63);
        __syncthreads();
        if (tid < NCLSP) {
            int o = (b * NSUB + sub0) * NCLSP + tid;
            #pragma unroll
            for (int h = 0; h < 4; h++) {
                g_hist[o + h * NCLSP] = hist[h][tid];
                g_fo[o + h * NCLSP]   = fo[h][tid];
            }
        }
    } else {
        int idx = (blockIdx.x - HIST_BLOCKS) * 256 + tid;
        if (idx < TAB_TOTAL) {
            int cls    = idx % NCLSP;
            int rest   = idx / NCLSP;
            int bucket = rest % NBUCK;
            int q      = rest / NBUCK;
            float2 r = make_float2(0.f, 0.f);
            if (cls < NCLS) {
                int dt = q / NPH, tp = q % NPH;
                int d  = cls % 10, p = cls / 10;
                int m  = tp - p; if (m < 0) m += NPH;
                float c = C[0], e = eps[0], vd = v[0];
                float L   = asf_f() * s_of(dt, c, e) * s_of(d, c, e) * cosm_f(m);
                float off = -56.0f + 100.0f * (float)bucket;
                float x   = expf(fminf(L - off, 60.0f)); // clamp hits only count-0 entries
                r = make_float2(x, x * vv0_of(d, c, e, vd));
            }
            g_tab[idx] = r;
        }
    }
}

// ---------------- K2: prefix + thresholds + cumulative-histogram softmax ------
__global__ void __launch_bounds__(512) k_main(
    const int*   __restrict__ tokens,
    const float* __restrict__ C,        const float* __restrict__ eps,
    const float* __restrict__ o_scale,  const float* __restrict__ g_base,
    const float* __restrict__ g_slope,  const float* __restrict__ carry_amp,
    float* __restrict__ out)
{
    extern __shared__ uint16_t cnt_sh[];   // [CHUNK][NCLSP] inclusive cumulative counts
    __shared__ int   tok_sh[CHUNK];
    __shared__ int   cls_sh[CHUNK];
    __shared__ int   foS[NCLSP];
    __shared__ int   baseA[NCLSP], baseB[NCLSP];
    __shared__ int   t1S[NCLS], t2S[NCLS];
    __shared__ float sdf[NV], cmf[NPH];

    int b   = blockIdx.x >> 4;
    int ch  = blockIdx.x & 15;
    int tid = threadIdx.x;
    int T0  = ch * CHUNK;

    float c  = C[0], ee = eps[0];

    if (tid < CHUNK) {
        int tk = tokens[b * LSEQ + T0 + tid];
        tok_sh[tid] = tk;
        cls_sh[tid] = tk + 10 * ((T0 + tid) % NPH);
    }
    if (tid < NV)  sdf[tid] = s_of(tid, c, ee);
    if (tid < NPH) cmf[tid] = cosm_f(tid);
    if (tid < NCLS) { t1S[tid] = 1 << 28; t2S[tid] = 1 << 28; }

    // per-class prefix bases for both chunk halves + global first-occurrence
    if (tid >= 256 && tid < 256 + NCLSP) {
        int cl = tid - 256;
        int mn = 1 << 28, base = 0, hA = 0;
        int sub_lo = ch * 2;
        #pragma unroll
        for (int ss = 0; ss < NSUB; ss++) {
            int o = (b * NSUB + ss) * NCLSP + cl;
            int h = g_hist[o];
            int f = g_fo[o];
            if (ss < sub_lo) base += h;
            if (ss == sub_lo) hA = h;
            mn = min(mn, f + ss * SUB);
        }
        foS[cl]   = mn;
        baseA[cl] = base;
        baseB[cl] = base + hA;
    }
    __syncthreads();

    // inclusive cumulative per-class counts, two 64-row halves in parallel
    if (tid < NCLSP) {
        int cl = tid, cnt = baseA[cl];
        #pragma unroll 8
        for (int p = 0; p < SUB; p++) {
            cnt += (cls_sh[p] == cl);
            cnt_sh[p * NCLSP + cl] = (uint16_t)cnt;
        }
    } else if (tid >= 256 && tid < 256 + NCLSP) {
        int cl = tid - 256, cnt = baseB[cl];
        #pragma unroll 8
        for (int p = SUB; p < CHUNK; p++) {
            cnt += (cls_sh[p] == cl);
            cnt_sh[p * NCLSP + cl] = (uint16_t)cnt;
        }
    }

    // bucket thresholds for all 190 query classes (3610 tasks over 512 threads)
    float A = asf_f();
    for (int task = tid; task < NCLS * NPH; task += 512) {
        int q = task / NPH, p = task % NPH;
        int m = q % NPH - p; if (m < 0) m += NPH;
        float base = A * sdf[q / NPH] * cmf[m];
        int l1 = 1 << 28, l2 = 1 << 28;
        #pragma unroll
        for (int d = 0; d < NV; d++) {
            float L = base * sdf[d];
            int f = foS[d + 10 * p];
            if (L >= -6.0f)  l1 = min(l1, f);
            if (L >=  94.0f) l2 = min(l2, f);
        }
        atomicMin(&t1S[q], l1);
        atomicMin(&t2S[q], l2);
    }
    __syncthreads();

    float osc = o_scale[0];
    float ga = g_base[0], gc = g_slope[0], ca = carry_amp[0];

    int w = tid >> 5, lane = tid & 31;      // 16 warps, 8 rows each
    const uint32_t* cnt32 = (const uint32_t*)cnt_sh;

    #pragma unroll 4
    for (int rr = 0; rr < 8; rr++) {
        int r  = w * 8 + rr;
        int t  = T0 + r;
        int dt = tok_sh[r];
        int q  = dt * NPH + (t % NPH);
        int bucket = (t >= t1S[q]) + (t >= t2S[q]);

        const float4* Tb = (const float4*)(g_tab + (q * NBUCK + bucket) * NCLSP) + lane * 3;
        float4 e0 = __ldg(Tb + 0);
        float4 e1 = __ldg(Tb + 1);
        float4 e2 = __ldg(Tb + 2);

        int base = r * (NCLSP / 2) + lane * 3;   // conflict-free: 3 coprime 32
        uint32_t u0 = cnt32[base], u1 = cnt32[base + 1], u2 = cnt32[base + 2];
        float c0 = (float)(u0 & 0xffff), c1 = (float)(u0 >> 16);
        float c2 = (float)(u1 & 0xffff), c3 = (float)(u1 >> 16);
        float c4 = (float)(u2 & 0xffff), c5 = (float)(u2 >> 16);

        float den = c0 * e0.x + c1 * e0.z + c2 * e1.x + c3 * e1.z + c4 * e2.x + c5 * e2.z;
        float num = c0 * e0.y + c1 * e0.w + c2 * e1.y + c3 * e1.w + c4 * e2.y + c5 * e2.w;

        #pragma unroll
        for (int o = 16; o; o >>= 1) {
            den += __shfl_xor_sync(0xffffffffu, den, o);
            num += __shfl_xor_sync(0xffffffffu, num, o);
        }
        float attn = num / den;

        // fused epilogue (mirrors reference fp32 math exactly)
        float h0 = c - ee * (float)(dt * dt);
        float h1 = -(float)dt + osc * attn;
        float rn = rsqrtf((h0 * h0 + h1 * h1) * 0.5f + 1e-6f);
        float hn0 = h0 * rn, hn1 = h1 * rn;
        float g0  = hn0 * ga + hn1 * gc;
        float g1  = hn0 * (ga - gc / c) + hn1 * gc;
        float carry = ca * (fmaxf(g1, 0.f) * hn0 - fmaxf(g0, 0.f) * hn0);
        float h1c = h1 + carry;
        float r2  = rsqrtf((h0 * h0 + h1c * h1c) * 0.5f + 1e-6f);
        const float inv_cn = 0.7071067811865475f;      // 1/sqrt(MODEL_DIM)
        float a0o = h0  * r2 * (0.1f * c * inv_cn);
        float a1o = h1c * r2 * (-c * 0.02f * inv_cn);  // -c/(50*sqrt2)
        if (lane < NV) {
            float t0  = c - ee * (float)(lane * lane);
            float t1v = -(float)lane;
            out[(b * LSEQ + t) * NV + lane] = a0o * t0 + a1o * t1v;
        }
    }
}

// ---------------- launch ----------------
extern "C" void kernel_launch(void* const* d_in, const int* in_sizes, int n_in,
                              void* d_out, int out_size) {
    const int*   tokens    = (const int*)  d_in[0];
    const float* C         = (const float*)d_in[1];
    const float* eps       = (const float*)d_in[2];
    const float* v         = (const float*)d_in[3];
    const float* o_scale   = (const float*)d_in[4];
    const float* g_base    = (const float*)d_in[5];
    const float* g_slope   = (const float*)d_in[6];
    const float* carry_amp = (const float*)d_in[7];
    float* out = (float*)d_out;

    const int smem = CHUNK * NCLSP * (int)sizeof(uint16_t);   // 49152
    cudaFuncSetAttribute(k_main, cudaFuncAttributeMaxDynamicSharedMemorySize, smem);

    k1<<<HIST_BLOCKS + TAB_BLOCKS, 256>>>(tokens, C, eps, v);
    k_main<<<NB * NCHUNK, 512, smem>>>(tokens, C, eps, o_scale, g_base, g_slope,
                                       carry_amp, out);
}

// round 11
// speedup vs baseline: 1.4773x; 1.1236x over previous
#include <cuda_runtime.h>
#include <math.h>
#include <stdint.h>

#define NB     16
#define LSEQ   2048
#define NV     10
#define NPH    19
#define NCLS   190
#define NCLSP  192
#define NBUCK  3
#define NCHUNK 16
#define CHUNK  128
#define NSUB   32                                 // 64-position subchunks per batch
#define SUB    64
#define TAB_TOTAL (NCLS * NBUCK * NCLSP)          // 109440
#define TAB_BLOCKS ((TAB_TOTAL + 255) / 256)      // 428
#define THR_BLOCKS NB                             // 16 per-batch threshold blocks
#define HIST_BLOCKS 128                           // 4 subchunks (256 pos) per block

// ---------------- device scratch (static, allocation-free) ----------------
__device__ int g_hist64 [NB * NSUB   * NCLSP];    // 64-gran histograms
__device__ int g_hist128[NB * NCHUNK * NCLSP];    // 128-gran histograms
__device__ int g_t1[NB * NCLS];
__device__ int g_t2[NB * NCLS];
__device__ __align__(16) float2 g_tab[TAB_TOTAL]; // {e, e*vv0} per (q,bucket,cls)

// ---------------- fp32 constants (no fp64 anywhere) ----------------
__device__ __forceinline__ float omega_f() { return 6.28318530717958647692f / 19.0f; }
// cancellation-free: cos(.3w)-cos(.7w) = 2 sin(.5w) sin(.2w); ATTN_SCALE = amp/2
__device__ __forceinline__ float asf_f() {
    float om = omega_f();
    return 2.302585092994046f / (4.0f * sinf(0.5f * om) * sinf(0.2f * om));
}
__device__ __forceinline__ float cosm_f(int m) {   // cos(om*m - phi), phi = om*10.3
    return cosf(omega_f() * ((float)m - 10.3f));
}
__device__ __forceinline__ float s_of(int d, float c, float e) {
    float h0 = c - e * (float)(d * d);
    float h1 = -(float)d;
    float r  = rsqrtf((h0 * h0 + h1 * h1) * 0.5f + 1e-6f);
    float hn0 = h0 * r;
    return hn0 * rsqrtf(hn0 * hn0 * 0.5f + 1e-6f);
}
__device__ __forceinline__ float vv0_of(int d, float c, float e, float v) {
    float h0 = c - e * (float)(d * d);
    float h1 = -(float)d;
    float r  = rsqrtf((h0 * h0 + h1 * h1) * 0.5f + 1e-6f);
    return h1 * r * v;
}

// ---------------- K1: three independent segments in one launch ----------------
//   blocks [0,16):        per-batch bucket thresholds (tokens -> fo -> t1/t2)
//   blocks [16,144):      sub-chunk histograms (64- and 128-gran)
//   blocks [144,144+428): exp table
__global__ __launch_bounds__(256) void k1(const int* __restrict__ tokens,
                                          const float* __restrict__ C,
                                          const float* __restrict__ eps,
                                          const float* __restrict__ v) {
    int tid = threadIdx.x;
    if (blockIdx.x < THR_BLOCKS) {
        int b = blockIdx.x;
        __shared__ int   foS[NCLSP];
        __shared__ float sdf[NV], cmf[NPH];
        __shared__ int   t1S[NCLS], t2S[NCLS];
        float c = C[0], e = eps[0];
        if (tid < NCLSP) foS[tid] = 1 << 20;
        if (tid < NV)    sdf[tid] = s_of(tid, c, e);
        if (tid < NPH)   cmf[tid] = cosm_f(tid);
        if (tid < NCLS)  { t1S[tid] = 1 << 28; t2S[tid] = 1 << 28; }
        __syncthreads();
        const int4* tp4 = (const int4*)(tokens + b * LSEQ);
        #pragma unroll
        for (int i = 0; i < 2; i++) {
            int4 tv = tp4[tid * 2 + i];
            int s0 = tid * 8 + i * 4;
            atomicMin(&foS[tv.x + 10 * ((s0    ) % NPH)], s0);
            atomicMin(&foS[tv.y + 10 * ((s0 + 1) % NPH)], s0 + 1);
            atomicMin(&foS[tv.z + 10 * ((s0 + 2) % NPH)], s0 + 2);
            atomicMin(&foS[tv.w + 10 * ((s0 + 3) % NPH)], s0 + 3);
        }
        __syncthreads();
        float A = asf_f();
        for (int task = tid; task < NCLS * NPH; task += 256) {
            int q = task / NPH, p = task % NPH;
            int m = q % NPH - p; if (m < 0) m += NPH;
            float base = A * sdf[q / NPH] * cmf[m];
            int l1 = 1 << 28, l2 = 1 << 28;
            #pragma unroll
            for (int d = 0; d < NV; d++) {
                float L = base * sdf[d];
                int f = foS[d + 10 * p];
                if (L >= -6.0f)  l1 = min(l1, f);
                if (L >=  94.0f) l2 = min(l2, f);
            }
            atomicMin(&t1S[q], l1);
            atomicMin(&t2S[q], l2);
        }
        __syncthreads();
        if (tid < NCLS) {
            g_t1[b * NCLS + tid] = t1S[tid];
            g_t2[b * NCLS + tid] = t2S[tid];
        }
    } else if (blockIdx.x < THR_BLOCKS + HIST_BLOCKS) {
        __shared__ int hist[4][NCLSP];
        int bx   = blockIdx.x - THR_BLOCKS;
        int b    = bx >> 3;                  // 16 batches * 8 blocks
        int sub0 = (bx & 7) * 4;             // four 64-pos subchunks per block
        if (tid < NCLSP) {
            #pragma unroll
            for (int h = 0; h < 4; h++) hist[h][tid] = 0;
        }
        __syncthreads();
        int s   = sub0 * SUB + tid;          // 256 positions = 4 subchunks
        int cls = tokens[b * LSEQ + s] + 10 * (s % NPH);
        atomicAdd(&hist[tid >> 6][cls], 1);
        __syncthreads();
        if (tid < NCLSP) {
            int o64 = (b * NSUB + sub0) * NCLSP + tid;
            #pragma unroll
            for (int h = 0; h < 4; h++) g_hist64[o64 + h * NCLSP] = hist[h][tid];
            int o128 = (b * NCHUNK + sub0 / 2) * NCLSP + tid;
            g_hist128[o128]         = hist[0][tid] + hist[1][tid];
            g_hist128[o128 + NCLSP] = hist[2][tid] + hist[3][tid];
        }
    } else {
        int idx = (blockIdx.x - THR_BLOCKS - HIST_BLOCKS) * 256 + tid;
        if (idx < TAB_TOTAL) {
            int cls    = idx % NCLSP;
            int rest   = idx / NCLSP;
            int bucket = rest % NBUCK;
            int q      = rest / NBUCK;
            float2 r = make_float2(0.f, 0.f);
            if (cls < NCLS) {
                int dt = q / NPH, tp = q % NPH;
                int d  = cls % 10, p = cls / 10;
                int m  = tp - p; if (m < 0) m += NPH;
                float c = C[0], e = eps[0], vd = v[0];
                float L   = asf_f() * s_of(dt, c, e) * s_of(d, c, e) * cosm_f(m);
                float off = -56.0f + 100.0f * (float)bucket;
                float x   = expf(fminf(L - off, 60.0f)); // clamp hits only count-0 entries
                r = make_float2(x, x * vv0_of(d, c, e, vd));
            }
            g_tab[idx] = r;
        }
    }
}

// ---------------- K2: cumulative-histogram softmax + fused epilogue ----------
__global__ void __launch_bounds__(512) k_main(
    const int*   __restrict__ tokens,
    const float* __restrict__ C,        const float* __restrict__ eps,
    const float* __restrict__ o_scale,  const float* __restrict__ g_base,
    const float* __restrict__ g_slope,  const float* __restrict__ carry_amp,
    float* __restrict__ out)
{
    extern __shared__ uint16_t cnt_sh[];   // [CHUNK][NCLSP] inclusive cumulative counts
    __shared__ int tok_sh[CHUNK];
    __shared__ int cls_sh[CHUNK];
    __shared__ int baseA[NCLSP], baseB[NCLSP];
    __shared__ int t1S[NCLS], t2S[NCLS];

    int b   = blockIdx.x >> 4;
    int ch  = blockIdx.x & 15;
    int tid = threadIdx.x;
    int T0  = ch * CHUNK;

    if (tid < CHUNK) {
        int tk = tokens[b * LSEQ + T0 + tid];
        tok_sh[tid] = tk;
        cls_sh[tid] = tk + 10 * ((T0 + tid) % NPH);
    }
    if (tid < NCLS) t1S[tid] = g_t1[b * NCLS + tid];
    else if (tid >= 256 && tid < 256 + NCLS) {
        int q = tid - 256;
        t2S[q] = g_t2[b * NCLS + q];
    }
    // per-class prefix bases for both chunk halves (threads 320..511)
    if (tid >= 320) {
        int cl = tid - 320;
        int basec = 0;
        for (int cc = 0; cc < ch; cc++)
            basec += g_hist128[(b * NCHUNK + cc) * NCLSP + cl];
        baseA[cl] = basec;
        baseB[cl] = basec + g_hist64[(b * NSUB + 2 * ch) * NCLSP + cl];
    }
    __syncthreads();

    // inclusive cumulative per-class counts, two 64-row halves in parallel
    if (tid < NCLSP) {
        int cl = tid, cnt = baseA[cl];
        #pragma unroll 8
        for (int p = 0; p < SUB; p++) {
            cnt += (cls_sh[p] == cl);
            cnt_sh[p * NCLSP + cl] = (uint16_t)cnt;
        }
    } else if (tid >= 256 && tid < 256 + NCLSP) {
        int cl = tid - 256, cnt = baseB[cl];
        #pragma unroll 8
        for (int p = SUB; p < CHUNK; p++) {
            cnt += (cls_sh[p] == cl);
            cnt_sh[p * NCLSP + cl] = (uint16_t)cnt;
        }
    }
    __syncthreads();

    float c   = C[0],      ee = eps[0],     osc = o_scale[0];
    float ga  = g_base[0], gc = g_slope[0], ca  = carry_amp[0];

    int w = tid >> 5, lane = tid & 31;      // 16 warps, 8 rows each
    const uint32_t* cnt32 = (const uint32_t*)cnt_sh;

    #pragma unroll
    for (int rr = 0; rr < 8; rr++) {
        int r  = w * 8 + rr;
        int t  = T0 + r;
        int dt = tok_sh[r];
        int q  = dt * NPH + (t % NPH);
        int bucket = (t >= t1S[q]) + (t >= t2S[q]);

        const float4* Tb = (const float4*)(g_tab + (q * NBUCK + bucket) * NCLSP) + lane * 3;
        float4 e0 = __ldg(Tb + 0);
        float4 e1 = __ldg(Tb + 1);
        float4 e2 = __ldg(Tb + 2);

        int base = r * (NCLSP / 2) + lane * 3;   // conflict-free: 3 coprime 32
        uint32_t u0 = cnt32[base], u1 = cnt32[base + 1], u2 = cnt32[base + 2];
        float c0 = (float)(u0 & 0xffff), c1 = (float)(u0 >> 16);
        float c2 = (float)(u1 & 0xffff), c3 = (float)(u1 >> 16);
        float c4 = (float)(u2 & 0xffff), c5 = (float)(u2 >> 16);

        float den = c0 * e0.x + c1 * e0.z + c2 * e1.x + c3 * e1.z + c4 * e2.x + c5 * e2.z;
        float num = c0 * e0.y + c1 * e0.w + c2 * e1.y + c3 * e1.w + c4 * e2.y + c5 * e2.w;

        #pragma unroll
        for (int o = 16; o; o >>= 1) {
            den += __shfl_xor_sync(0xffffffffu, den, o);
            num += __shfl_xor_sync(0xffffffffu, num, o);
        }
        float attn = __fdividef(num, den);

        // fused epilogue (mirrors reference fp32 math)
        float h0 = c - ee * (float)(dt * dt);
        float h1 = -(float)dt + osc * attn;
        float rn = rsqrtf((h0 * h0 + h1 * h1) * 0.5f + 1e-6f);
        float hn0 = h0 * rn, hn1 = h1 * rn;
        float g0  = hn0 * ga + hn1 * gc;
        float g1  = hn0 * (ga - gc / c) + hn1 * gc;
        float carry = ca * (fmaxf(g1, 0.f) * hn0 - fmaxf(g0, 0.f) * hn0);
        float h1c = h1 + carry;
        float r2  = rsqrtf((h0 * h0 + h1c * h1c) * 0.5f + 1e-6f);
        const float inv_cn = 0.7071067811865475f;      // 1/sqrt(MODEL_DIM)
        float a0o = h0  * r2 * (0.1f * c * inv_cn);
        float a1o = h1c * r2 * (-c * 0.02f * inv_cn);  // -c/(50*sqrt2)
        if (lane < NV) {
            float t0  = c - ee * (float)(lane * lane);
            float t1v = -(float)lane;
            out[(b * LSEQ + t) * NV + lane] = a0o * t0 + a1o * t1v;
        }
    }
}

// ---------------- launch ----------------
extern "C" void kernel_launch(void* const* d_in, const int* in_sizes, int n_in,
                              void* d_out, int out_size) {
    const int*   tokens    = (const int*)  d_in[0];
    const float* C         = (const float*)d_in[1];
    const float* eps       = (const float*)d_in[2];
    const float* v         = (const float*)d_in[3];
    const float* o_scale   = (const float*)d_in[4];
    const float* g_base    = (const float*)d_in[5];
    const float* g_slope   = (const float*)d_in[6];
    const float* carry_amp = (const float*)d_in[7];
    float* out = (float*)d_out;

    const int smem = CHUNK * NCLSP * (int)sizeof(uint16_t);   // 49152
    cudaFuncSetAttribute(k_main, cudaFuncAttributeMaxDynamicSharedMemorySize, smem);

    k1<<<THR_BLOCKS + HIST_BLOCKS + TAB_BLOCKS, 256>>>(tokens, C, eps, v);
    k_main<<<NB * NCHUNK, 512, smem>>>(tokens, C, eps, o_scale, g_base, g_slope,
                                       carry_amp, out);
}

// round 12
// speedup vs baseline: 1.5854x; 1.0732x over previous
#include <cuda_runtime.h>
#include <math.h>
#include <stdint.h>

#define NB     16
#define LSEQ   2048
#define NV     10
#define NPH    19
#define NCLS   190
#define NCLSP  192
#define NBUCK  3
#define NCH64  32                                 // 64-row chunks per batch
#define CH64   64
#define NSUB32 64                                 // 32-position subchunks per batch
#define TAB_TOTAL (NCLS * NBUCK * NCLSP)          // 109440
#define TAB_BLOCKS ((TAB_TOTAL + 255) / 256)      // 428
#define THR_BLOCKS NB                             // 16 per-batch threshold blocks
#define HIST_BLOCKS 128                           // 256 positions per block

// ---------------- device scratch (static, allocation-free) ----------------
__device__ int g_hist32[NB * NSUB32 * NCLSP];     // 32-gran histograms
__device__ int g_hist64[NB * NCH64  * NCLSP];     // 64-gran histograms
__device__ int g_t1[NB * NCLS];
__device__ int g_t2[NB * NCLS];
__device__ __align__(16) float2 g_tab[TAB_TOTAL]; // {e, e*vv0} per (q,bucket,cls)

// ---------------- fp32 constants (no fp64 anywhere) ----------------
__device__ __forceinline__ float omega_f() { return 6.28318530717958647692f / 19.0f; }
// cancellation-free: cos(.3w)-cos(.7w) = 2 sin(.5w) sin(.2w); ATTN_SCALE = amp/2
__device__ __forceinline__ float asf_f() {
    float om = omega_f();
    return 2.302585092994046f / (4.0f * sinf(0.5f * om) * sinf(0.2f * om));
}
__device__ __forceinline__ float cosm_f(int m) {   // cos(om*m - phi), phi = om*10.3
    return cosf(omega_f() * ((float)m - 10.3f));
}
__device__ __forceinline__ float s_of(int d, float c, float e) {
    float h0 = c - e * (float)(d * d);
    float h1 = -(float)d;
    float r  = rsqrtf((h0 * h0 + h1 * h1) * 0.5f + 1e-6f);
    float hn0 = h0 * r;
    return hn0 * rsqrtf(hn0 * hn0 * 0.5f + 1e-6f);
}
__device__ __forceinline__ float vv0_of(int d, float c, float e, float v) {
    float h0 = c - e * (float)(d * d);
    float h1 = -(float)d;
    float r  = rsqrtf((h0 * h0 + h1 * h1) * 0.5f + 1e-6f);
    return h1 * r * v;
}

// ---------------- K1: three independent segments in one launch ----------------
//   blocks [0,16):        per-batch bucket thresholds (tokens -> fo -> t1/t2)
//   blocks [16,144):      32/64-gran histograms
//   blocks [144,144+428): exp table
__global__ __launch_bounds__(256) void k1(const int* __restrict__ tokens,
                                          const float* __restrict__ C,
                                          const float* __restrict__ eps,
                                          const float* __restrict__ v) {
    int tid = threadIdx.x;
    if (blockIdx.x < THR_BLOCKS) {
        int b = blockIdx.x;
        __shared__ int   foS[NCLSP];
        __shared__ float sdf[NV], cmf[NPH];
        __shared__ int   t1S[NCLS], t2S[NCLS];
        float c = C[0], e = eps[0];
        if (tid < NCLSP) foS[tid] = 1 << 20;
        if (tid < NV)    sdf[tid] = s_of(tid, c, e);
        if (tid < NPH)   cmf[tid] = cosm_f(tid);
        if (tid < NCLS)  { t1S[tid] = 1 << 28; t2S[tid] = 1 << 28; }
        __syncthreads();
        const int4* tp4 = (const int4*)(tokens + b * LSEQ);
        #pragma unroll
        for (int i = 0; i < 2; i++) {
            int4 tv = tp4[tid * 2 + i];
            int s0 = tid * 8 + i * 4;
            atomicMin(&foS[tv.x + 10 * ((s0    ) % NPH)], s0);
            atomicMin(&foS[tv.y + 10 * ((s0 + 1) % NPH)], s0 + 1);
            atomicMin(&foS[tv.z + 10 * ((s0 + 2) % NPH)], s0 + 2);
            atomicMin(&foS[tv.w + 10 * ((s0 + 3) % NPH)], s0 + 3);
        }
        __syncthreads();
        float A = asf_f();
        for (int task = tid; task < NCLS * NPH; task += 256) {
            int q = task / NPH, p = task % NPH;
            int m = q % NPH - p; if (m < 0) m += NPH;
            float base = A * sdf[q / NPH] * cmf[m];
            int l1 = 1 << 28, l2 = 1 << 28;
            #pragma unroll
            for (int d = 0; d < NV; d++) {
                float L = base * sdf[d];
                int f = foS[d + 10 * p];
                if (L >= -6.0f)  l1 = min(l1, f);
                if (L >=  94.0f) l2 = min(l2, f);
            }
            atomicMin(&t1S[q], l1);
            atomicMin(&t2S[q], l2);
        }
        __syncthreads();
        if (tid < NCLS) {
            g_t1[b * NCLS + tid] = t1S[tid];
            g_t2[b * NCLS + tid] = t2S[tid];
        }
    } else if (blockIdx.x < THR_BLOCKS + HIST_BLOCKS) {
        __shared__ int hist[8][NCLSP];
        int bx   = blockIdx.x - THR_BLOCKS;
        int b    = bx >> 3;                  // 16 batches * 8 blocks
        int part = bx & 7;                   // 256-position segment
        if (tid < NCLSP) {
            #pragma unroll
            for (int h = 0; h < 8; h++) hist[h][tid] = 0;
        }
        __syncthreads();
        int s   = part * 256 + tid;          // 8 x 32-pos subchunks
        int cls = tokens[b * LSEQ + s] + 10 * (s % NPH);
        atomicAdd(&hist[tid >> 5][cls], 1);
        __syncthreads();
        if (tid < NCLSP) {
            int o32 = (b * NSUB32 + part * 8) * NCLSP + tid;
            #pragma unroll
            for (int h = 0; h < 8; h++) g_hist32[o32 + h * NCLSP] = hist[h][tid];
            int o64 = (b * NCH64 + part * 4) * NCLSP + tid;
            #pragma unroll
            for (int h = 0; h < 4; h++)
                g_hist64[o64 + h * NCLSP] = hist[2 * h][tid] + hist[2 * h + 1][tid];
        }
    } else {
        int idx = (blockIdx.x - THR_BLOCKS - HIST_BLOCKS) * 256 + tid;
        if (idx < TAB_TOTAL) {
            int cls    = idx % NCLSP;
            int rest   = idx / NCLSP;
            int bucket = rest % NBUCK;
            int q      = rest / NBUCK;
            float2 r = make_float2(0.f, 0.f);
            if (cls < NCLS) {
                int dt = q / NPH, tp = q % NPH;
                int d  = cls % 10, p = cls / 10;
                int m  = tp - p; if (m < 0) m += NPH;
                float c = C[0], e = eps[0], vd = v[0];
                float L   = asf_f() * s_of(dt, c, e) * s_of(d, c, e) * cosm_f(m);
                float off = -56.0f + 100.0f * (float)bucket;
                float x   = expf(fminf(L - off, 60.0f)); // clamp hits only count-0 entries
                r = make_float2(x, x * vv0_of(d, c, e, vd));
            }
            g_tab[idx] = r;
        }
    }
}

// ---------------- K2: cumulative-histogram softmax + fused epilogue ----------
// 512 blocks of 64 rows; 16 warps x 4 rows -> 8192 warps chip-wide (occ ~86%)
__global__ void __launch_bounds__(512) k_main(
    const int*   __restrict__ tokens,
    const float* __restrict__ C,        const float* __restrict__ eps,
    const float* __restrict__ o_scale,  const float* __restrict__ g_base,
    const float* __restrict__ g_slope,  const float* __restrict__ carry_amp,
    float* __restrict__ out)
{
    extern __shared__ uint16_t cnt_sh[];   // [CH64][NCLSP] inclusive cumulative counts
    __shared__ int tok_sh[CH64];
    __shared__ int cls_sh[CH64];
    __shared__ int baseA[NCLSP], baseB[NCLSP];
    __shared__ int t1S[NCLS], t2S[NCLS];

    int b   = blockIdx.x >> 5;
    int ch  = blockIdx.x & 31;              // 64-row chunk index
    int tid = threadIdx.x;
    int T0  = ch * CH64;

    if (tid >= 448) {                       // 64 threads: tokens + classes
        int i  = tid - 448;
        int tk = tokens[b * LSEQ + T0 + i];
        tok_sh[i] = tk;
        cls_sh[i] = tk + 10 * ((T0 + i) % NPH);
    }
    if (tid < NCLS) t1S[tid] = g_t1[b * NCLS + tid];
    else if (tid >= 192 && tid < 192 + NCLS) {
        int q = tid - 192;
        t2S[q] = g_t2[b * NCLS + q];
    }
    // per-class prefix bases for both 32-row halves (threads 256..447)
    if (tid >= 256 && tid < 256 + NCLSP) {
        int cl = tid - 256;
        int basec = 0;
        for (int cc = 0; cc < ch; cc++)
            basec += g_hist64[(b * NCH64 + cc) * NCLSP + cl];
        baseA[cl] = basec;
        baseB[cl] = basec + g_hist32[(b * NSUB32 + 2 * ch) * NCLSP + cl];
    }
    __syncthreads();

    // inclusive cumulative per-class counts, two 32-row halves in parallel
    if (tid < NCLSP) {
        int cl = tid, cnt = baseA[cl];
        #pragma unroll 8
        for (int p = 0; p < 32; p++) {
            cnt += (cls_sh[p] == cl);
            cnt_sh[p * NCLSP + cl] = (uint16_t)cnt;
        }
    } else if (tid >= 256 && tid < 256 + NCLSP) {
        int cl = tid - 256, cnt = baseB[cl];
        #pragma unroll 8
        for (int p = 32; p < CH64; p++) {
            cnt += (cls_sh[p] == cl);
            cnt_sh[p * NCLSP + cl] = (uint16_t)cnt;
        }
    }
    __syncthreads();

    float c   = C[0],      ee = eps[0],     osc = o_scale[0];
    float ga  = g_base[0], gc = g_slope[0], ca  = carry_amp[0];

    int w = tid >> 5, lane = tid & 31;      // 16 warps, 4 rows each
    const uint32_t* cnt32 = (const uint32_t*)cnt_sh;

    #pragma unroll
    for (int rr = 0; rr < 4; rr++) {
        int r  = w * 4 + rr;
        int t  = T0 + r;
        int dt = tok_sh[r];
        int q  = dt * NPH + (t % NPH);
        int bucket = (t >= t1S[q]) + (t >= t2S[q]);

        const float4* Tb = (const float4*)(g_tab + (q * NBUCK + bucket) * NCLSP) + lane * 3;
        float4 e0 = __ldg(Tb + 0);
        float4 e1 = __ldg(Tb + 1);
        float4 e2 = __ldg(Tb + 2);

        int base = r * (NCLSP / 2) + lane * 3;   // conflict-free: 3 coprime 32
        uint32_t u0 = cnt32[base], u1 = cnt32[base + 1], u2 = cnt32[base + 2];
        float c0 = (float)(u0 & 0xffff), c1 = (float)(u0 >> 16);
        float c2 = (float)(u1 & 0xffff), c3 = (float)(u1 >> 16);
        float c4 = (float)(u2 & 0xffff), c5 = (float)(u2 >> 16);

        float den = c0 * e0.x + c1 * e0.z + c2 * e1.x + c3 * e1.z + c4 * e2.x + c5 * e2.z;
        float num = c0 * e0.y + c1 * e0.w + c2 * e1.y + c3 * e1.w + c4 * e2.y + c5 * e2.w;

        #pragma unroll
        for (int o = 16; o; o >>= 1) {
            den += __shfl_xor_sync(0xffffffffu, den, o);
            num += __shfl_xor_sync(0xffffffffu, num, o);
        }
        float attn = __fdividef(num, den);

        // fused epilogue (mirrors reference fp32 math)
        float h0 = c - ee * (float)(dt * dt);
        float h1 = -(float)dt + osc * attn;
        float rn = rsqrtf((h0 * h0 + h1 * h1) * 0.5f + 1e-6f);
        float hn0 = h0 * rn, hn1 = h1 * rn;
        float g0  = hn0 * ga + hn1 * gc;
        float g1  = hn0 * (ga - gc / c) + hn1 * gc;
        float carry = ca * (fmaxf(g1, 0.f) * hn0 - fmaxf(g0, 0.f) * hn0);
        float h1c = h1 + carry;
        float r2  = rsqrtf((h0 * h0 + h1c * h1c) * 0.5f + 1e-6f);
        const float inv_cn = 0.7071067811865475f;      // 1/sqrt(MODEL_DIM)
        float a0o = h0  * r2 * (0.1f * c * inv_cn);
        float a1o = h1c * r2 * (-c * 0.02f * inv_cn);  // -c/(50*sqrt2)
        if (lane < NV) {
            float t0  = c - ee * (float)(lane * lane);
            float t1v = -(float)lane;
            out[(b * LSEQ + t) * NV + lane] = a0o * t0 + a1o * t1v;
        }
    }
}

// ---------------- launch ----------------
extern "C" void kernel_launch(void* const* d_in, const int* in_sizes, int n_in,
                              void* d_out, int out_size) {
    const int*   tokens    = (const int*)  d_in[0];
    const float* C         = (const float*)d_in[1];
    const float* eps       = (const float*)d_in[2];
    const float* v         = (const float*)d_in[3];
    const float* o_scale   = (const float*)d_in[4];
    const float* g_base    = (const float*)d_in[5];
    const float* g_slope   = (const float*)d_in[6];
    const float* carry_amp = (const float*)d_in[7];
    float* out = (float*)d_out;

    const int smem = CH64 * NCLSP * (int)sizeof(uint16_t);   // 24576
    cudaFuncSetAttribute(k_main, cudaFuncAttributeMaxDynamicSharedMemorySize, smem);

    k1<<<THR_BLOCKS + HIST_BLOCKS + TAB_BLOCKS, 256>>>(tokens, C, eps, v);
    k_main<<<NB * NCH64, 512, smem>>>(tokens, C, eps, o_scale, g_base, g_slope,
                                      carry_amp, out);
}